// round 7
// baseline (speedup 1.0000x reference)
#include <cuda_runtime.h>
#include <cuda_bf16.h>
#include <cstdint>
#include <cstddef>

#define B_   64
#define S_   512
#define E_   300
#define EP_  304
#define M_   32768

__device__ float g_x[M_ * EP_];
__device__ float g_w0pad[2][1024 * EP_];
__device__ float g_gx0[M_ * 2048];
__device__ float g_h1 [M_ * 512];
__device__ float g_gx1[M_ * 2048];
__device__ float g_h2 [M_ * 512];
__device__ float g_err[M_];

#define FMA2(acc, a, b) \
    asm("fma.rn.f32x2 %0, %1, %2, %0;" : "+l"(acc) : "l"(a), "l"(b))
#define PACK2(out, x) \
    asm("mov.b64 %0, {%1, %1};" : "=l"(out) : "f"(x))
#define UNPACK2(lo, hi, v) \
    asm("mov.b64 {%0, %1}, %2;" : "=f"(lo), "=f"(hi) : "l"(v))

__device__ __forceinline__ float sigm(float x) { return 1.0f / (1.0f + expf(-x)); }

__global__ void gather_kernel(const int* __restrict__ ids, const float* __restrict__ emb) {
    int m = blockIdx.x, s = m >> 6, b = m & 63;
    int id = ids[b * S_ + s];
    const float* src = emb + (size_t)id * E_;
    float* dst = g_x + (size_t)m * EP_;
    for (int e = threadIdx.x; e < EP_; e += blockDim.x)
        dst[e] = (e < E_) ? src[e] : 0.0f;
}

__global__ void padw_kernel(const float* __restrict__ wf, const float* __restrict__ wb) {
    int row = blockIdx.x & 1023, dir = blockIdx.x >> 10;
    const float* src = (dir ? wb : wf) + (size_t)row * E_;
    float* dst = g_w0pad[dir] + (size_t)row * EP_;
    for (int e = threadIdx.x; e < EP_; e += blockDim.x)
        dst[e] = (e < E_) ? src[e] : 0.0f;
}

// BM=128,BN=64,BK=16, double-buffered, fma.rn.f32x2 inner.
__global__ void sgemm_kernel(int layer, int dir,
                             const float* __restrict__ Wext,
                             const float* __restrict__ b1,
                             const float* __restrict__ b2) {
    const float* A; const float* W; float* C; int lda, K;
    if (layer == 0) { A = g_x;  lda = EP_; K = EP_; W = g_w0pad[dir]; C = g_gx0; }
    else            { A = g_h1; lda = 512; K = 512; W = Wext;         C = g_gx1; }
    const int coloff = dir << 10;

    __shared__ float As[2][16][132];
    __shared__ float Bs[2][16][68];

    const int tid = threadIdx.x;
    const int m0 = blockIdx.y * 128, n0 = blockIdx.x * 64;
    const int tx = tid & 15, ty = tid >> 4;
    const int arow = tid >> 2, acol = (tid & 3) * 4;

    unsigned long long acc2[4][4];
#pragma unroll
    for (int i = 0; i < 4; ++i)
#pragma unroll
        for (int j = 0; j < 4; ++j) acc2[i][j] = 0ULL;

    const int nIter = K >> 4;
    {
        float4 a0 = *(const float4*)(A + (size_t)(m0 + arow)      * lda + acol);
        float4 a1 = *(const float4*)(A + (size_t)(m0 + arow + 64) * lda + acol);
        float4 bv = *(const float4*)(W + (size_t)(n0 + arow)      * lda + acol);
        As[0][acol + 0][arow] = a0.x; As[0][acol + 1][arow] = a0.y;
        As[0][acol + 2][arow] = a0.z; As[0][acol + 3][arow] = a0.w;
        As[0][acol + 0][arow + 64] = a1.x; As[0][acol + 1][arow + 64] = a1.y;
        As[0][acol + 2][arow + 64] = a1.z; As[0][acol + 3][arow + 64] = a1.w;
        Bs[0][acol + 0][arow] = bv.x; Bs[0][acol + 1][arow] = bv.y;
        Bs[0][acol + 2][arow] = bv.z; Bs[0][acol + 3][arow] = bv.w;
    }
    __syncthreads();

    for (int it = 0; it < nIter; ++it) {
        const int cur = it & 1, nxt = cur ^ 1;
        const bool more = (it + 1 < nIter);
        float4 na0, na1, nbv;
        if (more) {
            const int k0 = (it + 1) << 4;
            na0 = *(const float4*)(A + (size_t)(m0 + arow)      * lda + k0 + acol);
            na1 = *(const float4*)(A + (size_t)(m0 + arow + 64) * lda + k0 + acol);
            nbv = *(const float4*)(W + (size_t)(n0 + arow)      * lda + k0 + acol);
        }
#pragma unroll
        for (int k = 0; k < 16; ++k) {
            const float* ar = &As[cur][k][ty * 8];
            ulonglong2 a01 = *(const ulonglong2*)ar;
            ulonglong2 a23 = *(const ulonglong2*)(ar + 4);
            float4 bw = *(const float4*)&Bs[cur][k][tx * 4];
            unsigned long long bd[4];
            PACK2(bd[0], bw.x); PACK2(bd[1], bw.y);
            PACK2(bd[2], bw.z); PACK2(bd[3], bw.w);
#pragma unroll
            for (int j = 0; j < 4; ++j) {
                FMA2(acc2[0][j], a01.x, bd[j]);
                FMA2(acc2[1][j], a01.y, bd[j]);
                FMA2(acc2[2][j], a23.x, bd[j]);
                FMA2(acc2[3][j], a23.y, bd[j]);
            }
        }
        if (more) {
            As[nxt][acol + 0][arow] = na0.x; As[nxt][acol + 1][arow] = na0.y;
            As[nxt][acol + 2][arow] = na0.z; As[nxt][acol + 3][arow] = na0.w;
            As[nxt][acol + 0][arow + 64] = na1.x; As[nxt][acol + 1][arow + 64] = na1.y;
            As[nxt][acol + 2][arow + 64] = na1.z; As[nxt][acol + 3][arow + 64] = na1.w;
            Bs[nxt][acol + 0][arow] = nbv.x; Bs[nxt][acol + 1][arow] = nbv.y;
            Bs[nxt][acol + 2][arow] = nbv.z; Bs[nxt][acol + 3][arow] = nbv.w;
        }
        __syncthreads();
    }

    const int ng = n0 + tx * 4;
    float bsum[4];
#pragma unroll
    for (int j = 0; j < 4; ++j) bsum[j] = b1[ng + j] + b2[ng + j];
#pragma unroll
    for (int p = 0; p < 4; ++p) {
        float lo[4], hi[4];
#pragma unroll
        for (int j = 0; j < 4; ++j) UNPACK2(lo[j], hi[j], acc2[p][j]);
        int m = m0 + ty * 8 + p * 2;
        float4 o0, o1;
        o0.x = lo[0] + bsum[0]; o0.y = lo[1] + bsum[1];
        o0.z = lo[2] + bsum[2]; o0.w = lo[3] + bsum[3];
        o1.x = hi[0] + bsum[0]; o1.y = hi[1] + bsum[1];
        o1.z = hi[2] + bsum[2]; o1.w = hi[3] + bsum[3];
        *(float4*)(C + (size_t)m * 2048 + coloff + ng) = o0;
        *(float4*)(C + (size_t)(m + 1) * 2048 + coloff + ng) = o1;
    }
}

// Cluster bi-LSTM: 128 CTAs, cluster(8). cid: dir=cid>>3, bg=cid&7.
// CTA rank owns 32 dims. thread=(tile=dim, bat); 4 gate dots in-register
// via fma.rn.f32x2, no reduce. smem floats:
// Wsl 32*1048=33536 @0, Hb[2][8][260]=4160 @33536, Gxs[2][8][136]=2176 @37696
#define LSTM_SMEM_BYTES (39872 * 4)

__global__ void __launch_bounds__(256, 1) __cluster_dims__(8, 1, 1)
lstm_kernel(int layer, const float* __restrict__ whh_f,
            const float* __restrict__ whh_b) {
    extern __shared__ float smf[];
    float* Wsl = smf;
    float* Hb  = smf + 33536;
    float* Gxs = smf + 37696;

    const int tid = threadIdx.x;
    uint32_t rank; asm("mov.u32 %0, %%cluster_ctarank;" : "=r"(rank));
    const int cid = blockIdx.x >> 3, dir = cid >> 3, bg = cid & 7;
    const int j0 = (int)(rank << 5);
    const float* whh  = dir ? whh_b : whh_f;
    const float* gx   = layer ? g_gx1 : g_gx0;
    float*       hout = layer ? g_h2  : g_h1;

    {   // W row (tileW, q) @ tileW*1048 + q*260  <-  whh[(q<<8)+j0+tileW]
        int rloc = tid >> 1, half = (tid & 1) << 7;
        int tw = rloc >> 2, q = rloc & 3;
        const float4* src = (const float4*)(whh + (size_t)((q << 8) + j0 + tw) * 256 + half);
        float4* dst = (float4*)(Wsl + tw * 1048 + q * 260 + half);
#pragma unroll
        for (int i = 0; i < 32; ++i) dst[i] = src[i];
    }
    for (int i = tid; i < 2080; i += 256) Hb[i] = 0.0f;
    const int pb = tid >> 5, pw = tid & 31, pq = pw >> 3, pe = pw & 7;
    {
        int s0 = dir ? 511 : 0;
        float4 gv = *(const float4*)(gx + (size_t)(s0 * 64 + bg * 8 + pb) * 2048
                                       + (dir << 10) + (pq << 8) + j0 + (pe << 2));
        *(float4*)(Gxs + pb * 136 + (pq << 5) + (pe << 2)) = gv;
    }
    uint32_t hb_peer[8];
    {
        uint32_t hb0 = (uint32_t)__cvta_generic_to_shared(Hb);
#pragma unroll
        for (int p = 0; p < 8; ++p)
            asm("mapa.shared::cluster.u32 %0, %1, %2;" : "=r"(hb_peer[p]) : "r"(hb0), "r"(p));
    }
    asm volatile("barrier.cluster.arrive.aligned;" ::: "memory");
    asm volatile("barrier.cluster.wait.aligned;" ::: "memory");

    const int tile = tid >> 3, bat = tid & 7;
    const float* wr = Wsl + tile * 1048;
    float creg = 0.0f;

    for (int t = 0; t < 512; ++t) {
        const int s = dir ? 511 - t : t;
        const int cur = t & 1, nxt = cur ^ 1;

        float4 gv;
        {
            int t2 = (t < 511) ? t + 1 : t;
            int s2 = dir ? 511 - t2 : t2;
            gv = *(const float4*)(gx + (size_t)(s2 * 64 + bg * 8 + pb) * 2048
                                    + (dir << 10) + (pq << 8) + j0 + (pe << 2));
        }

        unsigned long long a0 = 0, a1 = 0, a2 = 0, a3 = 0;
        const float* hb = Hb + cur * 2080 + bat * 260;
#pragma unroll 8
        for (int k = 0; k < 256; k += 4) {
            ulonglong2 hv = *(const ulonglong2*)(hb + k);
            ulonglong2 w0 = *(const ulonglong2*)(wr + k);
            ulonglong2 w1 = *(const ulonglong2*)(wr + 260 + k);
            ulonglong2 w2 = *(const ulonglong2*)(wr + 520 + k);
            ulonglong2 w3 = *(const ulonglong2*)(wr + 780 + k);
            FMA2(a0, w0.x, hv.x); FMA2(a0, w0.y, hv.y);
            FMA2(a1, w1.x, hv.x); FMA2(a1, w1.y, hv.y);
            FMA2(a2, w2.x, hv.x); FMA2(a2, w2.y, hv.y);
            FMA2(a3, w3.x, hv.x); FMA2(a3, w3.y, hv.y);
        }
        float gi, gf, gg, go;
        {
            float lo, hi;
            UNPACK2(lo, hi, a0); gi = lo + hi;
            UNPACK2(lo, hi, a1); gf = lo + hi;
            UNPACK2(lo, hi, a2); gg = lo + hi;
            UNPACK2(lo, hi, a3); go = lo + hi;
        }
        const float* gxb = Gxs + cur * 1088 + bat * 136;
        gi += gxb[tile]; gf += gxb[32 + tile];
        gg += gxb[64 + tile]; go += gxb[96 + tile];
        float c = sigm(gf) * creg + sigm(gi) * tanhf(gg);
        creg = c;
        float h = sigm(go) * tanhf(c);

        *(float4*)(Gxs + nxt * 1088 + pb * 136 + (pq << 5) + (pe << 2)) = gv;

        float h1 = __shfl_down_sync(0xffffffffu, h, 8);
        float h2 = __shfl_down_sync(0xffffffffu, h, 16);
        float h3 = __shfl_down_sync(0xffffffffu, h, 24);
        if ((tid & 24) == 0) {
            uint32_t off = (uint32_t)((nxt * 2080 + bat * 260 + j0 + ((tid >> 5) << 2)) << 2);
#pragma unroll
            for (int p = 0; p < 8; ++p)
                asm volatile("st.shared::cluster.v4.f32 [%0], {%1,%2,%3,%4};"
                             :: "r"(hb_peer[p] + off), "f"(h), "f"(h1), "f"(h2), "f"(h3)
                             : "memory");
        }
        hout[(size_t)(s * 64 + bg * 8 + bat) * 512 + (dir << 8) + j0 + tile] = h;
        asm volatile("barrier.cluster.arrive.aligned;" ::: "memory");
        asm volatile("barrier.cluster.wait.aligned;" ::: "memory");
    }
}

__global__ void score_kernel(const float* __restrict__ wlin,
                             const float* __restrict__ blin,
                             const float* __restrict__ labels,
                             const int* __restrict__ masks,
                             float* __restrict__ outs) {
    int w = blockIdx.x * 8 + (threadIdx.x >> 5);
    int lane = threadIdx.x & 31;
    int s = w >> 6, b = w & 63;
    const float* hp = g_h2 + (size_t)w * 512;
    float acc = 0.0f;
#pragma unroll
    for (int j = lane; j < 256; j += 32)
        acc += 0.5f * (hp[j] + hp[256 + j]) * wlin[j];
#pragma unroll
    for (int d = 16; d; d >>= 1) acc += __shfl_xor_sync(0xffffffffu, acc, d);
    if (lane == 0) {
        float sc = sigm(acc + blin[0]);
        int oi = b * S_ + s;
        outs[oi] = sc;
        float df = sc - labels[oi];
        g_err[oi] = df * df * (float)masks[oi];
    }
}

__global__ void loss_kernel(const int* __restrict__ masks,
                            float* __restrict__ out, int out_size) {
    __shared__ float sr[64];
    int b = threadIdx.x;
    if (b < 64) {
        float se = 0.0f, sm = 0.0f;
        for (int s = 0; s < S_; ++s) {
            se += g_err[b * S_ + s];
            sm += (float)masks[b * S_ + s];
        }
        sr[b] = se / sm;
    }
    __syncthreads();
    if (threadIdx.x == 0 && out_size > M_) {
        float t = 0.0f;
        for (int i = 0; i < 64; ++i) t += sr[i];
        out[M_] = t / 64.0f;
    }
}

extern "C" void kernel_launch(void* const* d_in, const int* in_sizes, int n_in,
                              void* d_out, int out_size) {
    const int*   ids    = (const int*)d_in[0];
    const float* labels = (const float*)d_in[1];
    const int*   masks  = (const int*)d_in[2];
    const float* emb    = (const float*)d_in[3];
    const float* wih0f = (const float*)d_in[4];
    const float* whh0f = (const float*)d_in[5];
    const float* bih0f = (const float*)d_in[6];
    const float* bhh0f = (const float*)d_in[7];
    const float* wih0b = (const float*)d_in[8];
    const float* whh0b = (const float*)d_in[9];
    const float* bih0b = (const float*)d_in[10];
    const float* bhh0b = (const float*)d_in[11];
    const float* wih1f = (const float*)d_in[12];
    const float* whh1f = (const float*)d_in[13];
    const float* bih1f = (const float*)d_in[14];
    const float* bhh1f = (const float*)d_in[15];
    const float* wih1b = (const float*)d_in[16];
    const float* whh1b = (const float*)d_in[17];
    const float* bih1b = (const float*)d_in[18];
    const float* bhh1b = (const float*)d_in[19];
    const float* wlin  = (const float*)d_in[20];
    const float* blin  = (const float*)d_in[21];
    float* out = (float*)d_out;

    static bool attr_done = false;
    if (!attr_done) {
        cudaFuncSetAttribute(lstm_kernel, cudaFuncAttributeMaxDynamicSharedMemorySize,
                             LSTM_SMEM_BYTES);
        attr_done = true;
    }

    gather_kernel<<<M_, 128>>>(ids, emb);
    padw_kernel<<<2048, 128>>>(wih0f, wih0b);

    dim3 gg(16, 256);
    sgemm_kernel<<<gg, 256>>>(0, 0, nullptr, bih0f, bhh0f);
    sgemm_kernel<<<gg, 256>>>(0, 1, nullptr, bih0b, bhh0b);

    lstm_kernel<<<128, 256, LSTM_SMEM_BYTES>>>(0, whh0f, whh0b);

    sgemm_kernel<<<gg, 256>>>(1, 0, wih1f, bih1f, bhh1f);
    sgemm_kernel<<<gg, 256>>>(1, 1, wih1b, bih1b, bhh1b);

    lstm_kernel<<<128, 256, LSTM_SMEM_BYTES>>>(1, whh1f, whh1b);

    score_kernel<<<M_ / 8, 256>>>(wlin, blin, labels, masks, out);
    loss_kernel<<<1, 64>>>(masks, out, out_size);
}